// round 1
// baseline (speedup 1.0000x reference)
#include <cuda_runtime.h>
#include <math.h>
#include <stdint.h>

#define B 4
#define L 1024
#define D 768
#define H 12
#define NE 42
#define MM 4
#define P 512
#define BLKSZ 64
#define NL 97
#define GB 12          // D / BLKSZ
#define KD 1536        // 2*D
#define ROWS (B*P)     // 2048

// ---------------- scratch (device globals; no allocation allowed) ----------
__device__ float g_eemb[B*NE*D];            // entity embeddings (logsumexp)
__device__ float g_eatt[B*NE*H*L];          // entity attentions (mean over mentions)
__device__ float g_htw[B*P*L];              // normalized per-pair channel weights
__device__ float g_rs[(size_t)ROWS*D];      // pooled context per pair
__device__ float g_zs[(size_t)ROWS*D];      // head extractor output
__device__ float g_zo[(size_t)ROWS*D];      // tail extractor output
__device__ float g_part[(size_t)GB*ROWS*NL];// per-group logits partials

// ---------------- kernel 1: entity embeddings (logsumexp over mentions) ----
__global__ void k_eemb(const float* __restrict__ seq, const int* __restrict__ mpos) {
    const int be = blockIdx.x;            // b*NE + e
    const int b = be / NE;
    __shared__ int pos[MM];
    if (threadIdx.x < MM) pos[threadIdx.x] = mpos[be*MM + threadIdx.x] + 1;
    __syncthreads();
    const float* sb = seq + (size_t)b * L * D;
    for (int d = threadIdx.x; d < D; d += blockDim.x) {
        float v0 = sb[(size_t)pos[0]*D + d];
        float v1 = sb[(size_t)pos[1]*D + d];
        float v2 = sb[(size_t)pos[2]*D + d];
        float v3 = sb[(size_t)pos[3]*D + d];
        float mx = fmaxf(fmaxf(v0, v1), fmaxf(v2, v3));
        float s = expf(v0-mx) + expf(v1-mx) + expf(v2-mx) + expf(v3-mx);
        g_eemb[(size_t)be*D + d] = mx + logf(s);
    }
}

// ---------------- kernel 2: entity attentions (mean over mention rows) -----
__global__ void k_eatt(const float* __restrict__ att, const int* __restrict__ mpos) {
    const int idx = blockIdx.x;           // (b*NE+e)*H + h
    const int h  = idx % H;
    const int be = idx / H;
    const int b  = be / NE;
    __shared__ int pos[MM];
    if (threadIdx.x < MM) pos[threadIdx.x] = mpos[be*MM + threadIdx.x] + 1;
    __syncthreads();
    const float* ab = att + (size_t)(b*H + h) * L * L;
    float* outp = g_eatt + ((size_t)be*H + h) * L;
    for (int l = threadIdx.x; l < L; l += blockDim.x) {
        float s = ab[(size_t)pos[0]*L + l] + ab[(size_t)pos[1]*L + l]
                + ab[(size_t)pos[2]*L + l] + ab[(size_t)pos[3]*L + l];
        outp[l] = 0.25f * s;
    }
}

// ---------------- kernel 3: per-pair channel weights, normalized -----------
__global__ void k_htw(const int* __restrict__ hts) {
    const int bp = blockIdx.x;            // b*P + p
    const int b  = bp / P;
    const int hi = hts[bp*2 + 0];
    const int ti = hts[bp*2 + 1];
    const float* eh = g_eatt + (size_t)(b*NE + hi) * H * L;
    const float* et = g_eatt + (size_t)(b*NE + ti) * H * L;
    const int tid = threadIdx.x;
    float w[4];
    float lsum = 0.f;
    #pragma unroll
    for (int r = 0; r < 4; r++) {
        const int l = tid + r*256;
        float acc = 0.f;
        #pragma unroll
        for (int hh = 0; hh < H; hh++)
            acc += eh[hh*L + l] * et[hh*L + l];
        w[r] = acc;
        lsum += acc;
    }
    __shared__ float red[256];
    red[tid] = lsum;
    __syncthreads();
    for (int s = 128; s > 0; s >>= 1) {
        if (tid < s) red[tid] += red[tid + s];
        __syncthreads();
    }
    const float total = red[0];
    // ht = (w/H) / (total/H + 1e-5)
    const float scale = 1.f / ((float)H * (total / (float)H + 1e-5f));
    float* outp = g_htw + (size_t)bp * L;
    #pragma unroll
    for (int r = 0; r < 4; r++)
        outp[tid + r*256] = w[r] * scale;
}

// ---------------- kernel 4: rs = ht_w @ seq (per-batch GEMM 512x768x1024) --
__global__ void k_rs(const float* __restrict__ seq) {
    const int b  = blockIdx.z;
    const int p0 = blockIdx.y * 64;
    const int n0 = blockIdx.x * 64;
    const float* A  = g_htw + (size_t)b * P * L;   // [P][L]
    const float* Bm = seq   + (size_t)b * L * D;   // [L][D]
    __shared__ float As[16][64];
    __shared__ float Bs[16][64];
    const int tid = threadIdx.x;
    const int tx = tid & 15, ty = tid >> 4;
    float acc[4][4] = {};
    for (int k0 = 0; k0 < L; k0 += 16) {
        {   // A tile: thread loads 4 consecutive k of one row
            const int m  = tid >> 2;
            const int kk = (tid & 3) * 4;
            const float4 v = *(const float4*)&A[(size_t)(p0 + m)*L + k0 + kk];
            As[kk+0][m] = v.x; As[kk+1][m] = v.y; As[kk+2][m] = v.z; As[kk+3][m] = v.w;
        }
        {   // B tile
            const int kr = tid >> 4;
            const int nn = (tid & 15) * 4;
            *(float4*)&Bs[kr][nn] = *(const float4*)&Bm[(size_t)(k0 + kr)*D + n0 + nn];
        }
        __syncthreads();
        #pragma unroll
        for (int k = 0; k < 16; k++) {
            const float4 a  = *(const float4*)&As[k][ty*4];
            const float4 bb = *(const float4*)&Bs[k][tx*4];
            float av[4] = {a.x, a.y, a.z, a.w};
            float bv[4] = {bb.x, bb.y, bb.z, bb.w};
            #pragma unroll
            for (int i = 0; i < 4; i++)
                #pragma unroll
                for (int j = 0; j < 4; j++)
                    acc[i][j] += av[i] * bv[j];
        }
        __syncthreads();
    }
    float* C = g_rs + (size_t)(b*P + p0) * D + n0;
    #pragma unroll
    for (int i = 0; i < 4; i++)
        #pragma unroll
        for (int j = 0; j < 4; j++)
            C[(size_t)(ty*4 + i)*D + tx*4 + j] = acc[i][j];
}

// ---- kernel 5: extractor z = tanh([gathered_emb, rs] @ W + bias) ----------
__global__ void k_extract(const float* __restrict__ W, const float* __restrict__ bias,
                          const int* __restrict__ hts, int which) {
    const int r0 = blockIdx.y * 64;       // row in [0, B*P)
    const int n0 = blockIdx.x * 64;
    float* outb = which ? g_zo : g_zs;
    __shared__ float As[16][64];
    __shared__ float Bs[16][64];
    __shared__ const float* arow[64];
    const int tid = threadIdx.x;
    if (tid < 64) {
        const int row = r0 + tid;
        const int b = row / P;
        const int e = hts[row*2 + which];
        arow[tid] = g_eemb + (size_t)(b*NE + e) * D;
    }
    __syncthreads();
    const int tx = tid & 15, ty = tid >> 4;
    float acc[4][4] = {};
    for (int k0 = 0; k0 < KD; k0 += 16) {
        {
            const int m  = tid >> 2;
            const int kk = (tid & 3) * 4;
            const int k  = k0 + kk;
            float4 v;
            if (k < D) v = *(const float4*)&arow[m][k];
            else       v = *(const float4*)&g_rs[(size_t)(r0 + m)*D + (k - D)];
            As[kk+0][m] = v.x; As[kk+1][m] = v.y; As[kk+2][m] = v.z; As[kk+3][m] = v.w;
        }
        {
            const int kr = tid >> 4;
            const int nn = (tid & 15) * 4;
            *(float4*)&Bs[kr][nn] = *(const float4*)&W[(size_t)(k0 + kr)*D + n0 + nn];
        }
        __syncthreads();
        #pragma unroll
        for (int k = 0; k < 16; k++) {
            const float4 a  = *(const float4*)&As[k][ty*4];
            const float4 bb = *(const float4*)&Bs[k][tx*4];
            float av[4] = {a.x, a.y, a.z, a.w};
            float bv[4] = {bb.x, bb.y, bb.z, bb.w};
            #pragma unroll
            for (int i = 0; i < 4; i++)
                #pragma unroll
                for (int j = 0; j < 4; j++)
                    acc[i][j] += av[i] * bv[j];
        }
        __syncthreads();
    }
    float* C = outb + (size_t)(r0) * D + n0;
    #pragma unroll
    for (int i = 0; i < 4; i++)
        #pragma unroll
        for (int j = 0; j < 4; j++)
            C[(size_t)(ty*4 + i)*D + tx*4 + j] =
                tanhf(acc[i][j] + bias[n0 + tx*4 + j]);
}

// ---- kernel 6: grouped bilinear logits, per-g partial sums ----------------
// logits[p,n] = sum_g sum_i zs[p,gi] * ( sum_j zo[p,gj] * W[(gi,j),n] )
__global__ void k_logits(const float* __restrict__ Wbi) {
    const int g  = blockIdx.y;
    const int r0 = blockIdx.x * 64;
    __shared__ float zos[64*64];
    __shared__ float Ws[64*NL + 32];       // +32 slack so unpredicated reads stay in-bounds
    const int tid = threadIdx.x;
    const int tx = tid & 31;               // 4 label slots: tx, tx+32, tx+64, tx+96
    const int ty = tid >> 5;               // 8 pair slots: ty + 8*pp

    // stage zo g-slice (64 pairs x 64 cols)
    for (int t = tid; t < 64*16; t += 256) {
        const int m  = t >> 4;
        const int c4 = (t & 15) * 4;
        *(float4*)&zos[m*64 + c4] =
            *(const float4*)&g_zo[(size_t)(r0 + m)*D + g*BLKSZ + c4];
    }

    float acc[8][4] = {};
    const float* Wg = Wbi + (size_t)g * BLKSZ * BLKSZ * NL;

    for (int i = 0; i < BLKSZ; i++) {
        __syncthreads();                   // protect Ws (also covers zos on i==0)
        const float* src = Wg + (size_t)i * BLKSZ * NL;
        for (int t = tid; t < BLKSZ*NL; t += 256) Ws[t] = src[t];
        __syncthreads();

        float tmp[8][4] = {};
        #pragma unroll 4
        for (int j = 0; j < BLKSZ; j++) {
            float wv[4];
            #pragma unroll
            for (int nn = 0; nn < 4; nn++)
                wv[nn] = Ws[j*NL + tx + nn*32];   // tail reads garbage, never stored
            #pragma unroll
            for (int pp = 0; pp < 8; pp++) {
                const float zo = zos[(ty + pp*8)*64 + j];   // warp-broadcast
                #pragma unroll
                for (int nn = 0; nn < 4; nn++) tmp[pp][nn] += zo * wv[nn];
            }
        }
        #pragma unroll
        for (int pp = 0; pp < 8; pp++) {
            const float zi = g_zs[(size_t)(r0 + ty + pp*8)*D + g*BLKSZ + i];
            #pragma unroll
            for (int nn = 0; nn < 4; nn++) acc[pp][nn] += zi * tmp[pp][nn];
        }
    }

    float* outp = g_part + ((size_t)g * ROWS + r0) * NL;
    #pragma unroll
    for (int pp = 0; pp < 8; pp++) {
        const int m = ty + pp*8;
        #pragma unroll
        for (int nn = 0; nn < 4; nn++) {
            const int n = tx + nn*32;
            if (n < NL) outp[(size_t)m*NL + n] = acc[pp][nn];
        }
    }
}

// ---- kernel 7: reduce partials over g, add bias ----------------------------
__global__ void k_reduce(const float* __restrict__ b_bi, float* __restrict__ out) {
    const int idx = blockIdx.x * 256 + threadIdx.x;
    if (idx >= ROWS * NL) return;
    const int n = idx % NL;
    float s = b_bi[n];
    #pragma unroll
    for (int g = 0; g < GB; g++)
        s += g_part[(size_t)g * (ROWS*NL) + idx];
    out[idx] = s;
}

// ---------------------------------------------------------------------------
extern "C" void kernel_launch(void* const* d_in, const int* in_sizes, int n_in,
                              void* d_out, int out_size) {
    const float* seq    = (const float*)d_in[0];
    const float* att    = (const float*)d_in[1];
    const int*   mpos   = (const int*)d_in[2];
    const int*   hts    = (const int*)d_in[3];
    const float* W_head = (const float*)d_in[4];
    const float* b_head = (const float*)d_in[5];
    const float* W_tail = (const float*)d_in[6];
    const float* b_tail = (const float*)d_in[7];
    const float* W_bi   = (const float*)d_in[8];
    const float* b_bi   = (const float*)d_in[9];
    float* out = (float*)d_out;

    k_eemb<<<B*NE, 256>>>(seq, mpos);
    k_eatt<<<B*NE*H, 256>>>(att, mpos);
    k_htw<<<B*P, 256>>>(hts);

    dim3 grs(D/64, P/64, B);
    k_rs<<<grs, 256>>>(seq);

    dim3 gex(D/64, ROWS/64);
    k_extract<<<gex, 256>>>(W_head, b_head, hts, 0);
    k_extract<<<gex, 256>>>(W_tail, b_tail, hts, 1);

    dim3 glg(ROWS/64, GB);
    k_logits<<<glg, 256>>>(W_bi);

    k_reduce<<<(ROWS*NL + 255)/256, 256>>>(b_bi, out);
}